// round 12
// baseline (speedup 1.0000x reference)
#include <cuda_runtime.h>
#include <cstdint>
#include <math.h>

// ---------------------------------------------------------------------------
// 2-layer LSTM (B=64, T=2048, D=64, H=512) + linear head + log_softmax.
//
// Persistent weight-stationary kernel. R12: DUAL BATCH STREAMS (32+32).
// Diagnosis: the gates stage is MUFU-bound (~10K cyc/round, rt 8/SMSP) and
// ran serially after the FMA-bound gemv. Streams are independent across the
// whole recurrence, so round r interleaves:
//   gemv(s0) | SYNC | [warps0-3: gates(s0)+publish] || [others: gemv(s1)]
//   | SYNC | [warps8-11: gates(s1)+publish] || [all: next round gemv(s0)]
// -> every SMSP always runs 1 MUFU-warp + 3 FMA-warps; gates and barrier
// latency hide under gemv. Per-stream counters; publish->wait slack = half
// a round. gemv keeps R11's k-parity weight sharing (1 batch/lane, LDG.32).
// ---------------------------------------------------------------------------

namespace {
constexpr int B_   = 64;
constexpr int T_   = 2048;
constexpr int D_   = 64;
constexpr int H_   = 512;
constexpr int OUT_ = 10;
constexpr int NCTA = 128;
constexpr int NTHR = 512;                 // 16 warps = 8 k-slices x 2 b-halves
constexpr int ROWS = 16;                  // gate rows per layer per CTA
constexpr int SB   = 32;                  // batches per stream
constexpr int K0   = H_ + D_;
constexpr int K1   = H_ + H_;

constexpr size_t OFF_W0  = 0;                                   // [576][16]
constexpr size_t OFF_W1  = OFF_W0 + (size_t)K0 * ROWS * 4;      //  36864
constexpr size_t OFF_GP  = OFF_W1 + (size_t)K1 * ROWS * 4;      // 102400
// gp: [2 stream][2 layer][8 slice][8 pair][32 b] u64 = 65536
constexpr size_t OFF_CST = OFF_GP + (size_t)4 * 8 * 8 * SB * 8; // 167936
constexpr size_t OFF_BIA = OFF_CST + 2048;                      // 169984
constexpr size_t SMEM_BYTES = OFF_BIA + 128;                    // 170112

constexpr int HV_STRIDE = 521;                  // head staging
constexpr size_t OFF_LG = (size_t)B_ * HV_STRIDE * 4;           // 133376
}

// Static device scratch (no runtime allocation).
__device__ float g_h1[(size_t)T_ * H_ * B_];   // layer0 h, [t][unit][b]
__device__ float g_h2[(size_t)T_ * H_ * B_];   // layer1 h, [t][unit][b]
__device__ float g_xT[(size_t)T_ * D_ * B_];   // x transposed, [t][k][b]
__device__ int   g_cnt0[T_ + 1];               // stream-0 round counters
__device__ int   g_cnt1[T_ + 1];               // stream-1 round counters

__device__ __forceinline__ void ffma2(uint64_t& acc, uint64_t a, uint64_t b) {
    asm("fma.rn.f32x2 %0, %1, %2, %0;" : "+l"(acc) : "l"(a), "l"(b));
}
__device__ __forceinline__ void addf2(uint64_t& acc, uint64_t a) {
    asm("add.rn.f32x2 %0, %0, %1;" : "+l"(acc) : "l"(a));
}
__device__ __forceinline__ uint64_t dup2(float x) {
    uint64_t r;
    asm("mov.b64 %0, {%1, %1};" : "=l"(r) : "f"(x));
    return r;
}
__device__ __forceinline__ float2 unpk(uint64_t v) {
    float2 f;
    asm("mov.b64 {%0, %1}, %2;" : "=f"(f.x), "=f"(f.y) : "l"(v));
    return f;
}
__device__ __forceinline__ int ld_acq(const int* p) {
    int v;
    asm volatile("ld.global.acquire.gpu.b32 %0, [%1];" : "=r"(v) : "l"(p));
    return v;
}
__device__ __forceinline__ void wait_ready(const int* p) {
    if ((threadIdx.x & 31) == 0) {
        while (ld_acq(p) < NCTA) {}
    }
    __syncwarp();
}
__device__ __forceinline__ float fast_sigmoid(float x) {
    return __fdividef(1.f, 1.f + __expf(-x));
}
__device__ __forceinline__ float fast_tanh(float x) {
    float a = fabsf(x);
    float t = __expf(-2.f * a);
    float r = __fdividef(1.f - t, 1.f + t);
    return copysignf(r, x);
}

// k-parity GEMV, 1 batch per lane: lane-half h handles rows k+h; per k-pair
// one coalesced LDG.32 row-segment per half + 4 LDS.128 shared across halves.
// a[p] accumulates row-pair p for this lane's single batch (f32x2 = 2 rows).
__device__ __forceinline__ void gemv1(uint64_t a[8],
                                      const float* __restrict__ wsm,
                                      const float* __restrict__ in,
                                      int kb, int ke, int b1, int h) {
#pragma unroll 8
    for (int k = kb; k < ke; k += 2) {
        int kk = k + h;
        uint64_t x = dup2(in[(size_t)kk * B_ + b1]);
        const ulonglong2* wv = (const ulonglong2*)(wsm + (size_t)kk * ROWS);
#pragma unroll
        for (int q = 0; q < 4; ++q) {
            ulonglong2 wp = wv[q];
            ffma2(a[2 * q],     wp.x, x);
            ffma2(a[2 * q + 1], wp.y, x);
        }
    }
}

// Combine k-parities (shfl 16) and store; lanes 0-15 write contiguous rows.
__device__ __forceinline__ void cstore(uint64_t a[8], uint64_t* __restrict__ gp,
                                       int ks, int b1, int lane) {
#pragma unroll
    for (int p = 0; p < 8; ++p) {
        unsigned long long o = __shfl_xor_sync(0xffffffffu,
                                               (unsigned long long)a[p], 16);
        addf2(a[p], (uint64_t)o);
    }
    if (lane < 16) {
#pragma unroll
        for (int p = 0; p < 8; ++p)
            gp[(size_t)(ks * 8 + p) * SB + b1] = a[p];
    }
}

// Gates for one stream: 128 threads, thread = (layer l, pair-half p, batch b).
__device__ __forceinline__ void gates_stage(int st, int it, int r,
                                            const uint64_t* __restrict__ gp,
                                            float* __restrict__ cst,
                                            const float* __restrict__ bias,
                                            int j0) {
    int l = it >> 6;
    int p = (it >> 5) & 1;
    int b = it & 31;
    bool act = l ? (r >= 1) : (r < T_);
    if (!act) return;
    const uint64_t* g = gp + (size_t)(st * 2 + l) * (8 * 8 * SB);
    uint64_t sg[4];
#pragma unroll
    for (int gq = 0; gq < 4; ++gq) {
        int pi = gq * 2 + p;
        uint64_t v = g[(size_t)pi * SB + b];
#pragma unroll
        for (int ss = 1; ss < 8; ++ss)
            addf2(v, g[((size_t)ss * 8 + pi) * SB + b]);
        sg[gq] = v;
    }
    float2 vi = unpk(sg[0]), vf = unpk(sg[1]);
    float2 vg = unpk(sg[2]), vo = unpk(sg[3]);
    const float* bb = bias + l * 16;
    int t = l ? (r - 1) : r;
    float* hout = l ? g_h2 : g_h1;
#pragma unroll
    for (int j2 = 0; j2 < 2; ++j2) {
        int j = 2 * p + j2;
        float gi = (j2 ? vi.y : vi.x) + bb[j];
        float gf = (j2 ? vf.y : vf.x) + bb[4 + j];
        float gg = (j2 ? vg.y : vg.x) + bb[8 + j];
        float go = (j2 ? vo.y : vo.x) + bb[12 + j];
        float si = fast_sigmoid(gi);
        float sf = fast_sigmoid(gf);
        float so = fast_sigmoid(go);
        float tg = fast_tanh(gg);
        int ci = ((st * 2 + l) * 4 + j) * SB + b;
        float c = sf * cst[ci] + si * tg;
        cst[ci] = c;
        hout[(size_t)t * H_ * B_ + (size_t)(j0 + j) * B_ + st * SB + b]
            = so * fast_tanh(c);
    }
}

// prep: zero counters + transpose x[b][t][k] -> g_xT[t][k][b]
__global__ void prep_kernel(const float* __restrict__ x) {
    __shared__ float tile[64][65];
    int t = blockIdx.x;
    if (threadIdx.x == 0) {
        g_cnt0[t] = 0;
        g_cnt1[t] = 0;
        if (t == 0) { g_cnt0[T_] = 0; g_cnt1[T_] = 0; }
    }
    for (int i = threadIdx.x; i < 64 * 64; i += blockDim.x) {
        int b = i >> 6, k = i & 63;
        tile[b][k] = x[(size_t)b * T_ * D_ + (size_t)t * D_ + k];
    }
    __syncthreads();
    for (int i = threadIdx.x; i < 64 * 64; i += blockDim.x) {
        int k = i >> 6, b = i & 63;
        g_xT[(size_t)t * D_ * B_ + (size_t)k * B_ + b] = tile[b][k];
    }
}

__global__ __launch_bounds__(NTHR, 1)
void lstm_kernel(const float* __restrict__ Wih0, const float* __restrict__ Whh0,
                 const float* __restrict__ bih0, const float* __restrict__ bhh0,
                 const float* __restrict__ Wih1, const float* __restrict__ Whh1,
                 const float* __restrict__ bih1, const float* __restrict__ bhh1,
                 const float* __restrict__ Wlin, const float* __restrict__ blin,
                 float* __restrict__ out) {
    extern __shared__ unsigned char smem[];
    float*    w0   = (float*)(smem + OFF_W0);      // [K0][16]
    float*    w1   = (float*)(smem + OFF_W1);      // [K1][16]
    uint64_t* gp   = (uint64_t*)(smem + OFF_GP);   // [2 st][2 l][8 s][8 p][32]
    float*    cst  = (float*)(smem + OFF_CST);     // [2 st][2 l][4 j][32]
    float*    bias = (float*)(smem + OFF_BIA);     // [2][16]

    const int tid  = threadIdx.x;
    const int lane = tid & 31;
    const int w    = tid >> 5;                     // warp 0..15
    const int ks   = w & 7;                        // k-slice 0..7
    const int bh   = w >> 3;                       // batch-half within stream
    const int h    = lane >> 4;                    // k-parity 0..1
    const int m    = lane & 15;
    const int b1   = bh * 16 + m;                  // batch 0..31 within stream
    const int j0   = blockIdx.x * 4;

    // ---- load weights (row r = gate*4 + j; k<H_ -> W_hh else W_ih) ----
    for (int idx = tid; idx < K0 * ROWS; idx += NTHR) {
        int k = idx >> 4, rr = idx & 15;
        int row = (rr >> 2) * H_ + j0 + (rr & 3);
        w0[idx] = (k < H_) ? Whh0[(size_t)row * H_ + k]
                           : Wih0[(size_t)row * D_ + (k - H_)];
    }
    for (int idx = tid; idx < K1 * ROWS; idx += NTHR) {
        int k = idx >> 4, rr = idx & 15;
        int row = (rr >> 2) * H_ + j0 + (rr & 3);
        w1[idx] = (k < H_) ? Whh1[(size_t)row * H_ + k]
                           : Wih1[(size_t)row * H_ + (k - H_)];
    }
    if (tid < 32) {
        int l = tid >> 4, rr = tid & 15;
        int row = (rr >> 2) * H_ + j0 + (rr & 3);
        bias[tid] = l ? (bih1[row] + bhh1[row]) : (bih0[row] + bhh0[row]);
    }
    cst[tid] = 0.f;                                // exactly 512 entries
    __syncthreads();

    const float* w0x  = w0 + (size_t)H_ * ROWS;    // layer0 x-ff rows
    const float* w1ff = w1 + (size_t)H_ * ROWS;    // layer1 h1-ff rows

#pragma unroll 1
    for (int r = 0; r <= T_; ++r) {
        // ================= stream 0 half =================
        if (r >= 1) wait_ready(&g_cnt0[r - 1]);
        {
            uint64_t a[8];
#pragma unroll
            for (int i = 0; i < 8; ++i) a[i] = 0ull;
            if (r < T_) {
                if (r >= 1)
                    gemv1(a, w0, g_h1 + (size_t)(r - 1) * H_ * B_,
                          ks * 64, ks * 64 + 64, b1, h);
                gemv1(a, w0x, g_xT + (size_t)r * D_ * B_,
                      ks * 8, ks * 8 + 8, b1, h);
            }
            cstore(a, gp, ks, b1, lane);                       // [0][0]
#pragma unroll
            for (int i = 0; i < 8; ++i) a[i] = 0ull;
            if (r >= 1) {
                gemv1(a, w1ff, g_h1 + (size_t)(r - 1) * H_ * B_,
                      ks * 64, ks * 64 + 64, b1, h);
                if (r >= 2)
                    gemv1(a, w1, g_h2 + (size_t)(r - 2) * H_ * B_,
                          ks * 64, ks * 64 + 64, b1, h);
            }
            cstore(a, gp + (size_t)1 * (8 * 8 * SB), ks, b1, lane); // [0][1]
        }
        __syncthreads();                                       // SYNC1
        if (tid < 128) {                                       // gates s0
            gates_stage(0, tid, r, gp, cst, bias, j0);
            __threadfence();
            asm volatile("bar.sync 1, 128;" ::: "memory");
            if (tid == 0) atomicAdd(&g_cnt0[r], 1);
        }

        // ================= stream 1 half =================
        if (r >= 1) wait_ready(&g_cnt1[r - 1]);
        {
            uint64_t a[8];
#pragma unroll
            for (int i = 0; i < 8; ++i) a[i] = 0ull;
            if (r < T_) {
                if (r >= 1)
                    gemv1(a, w0, g_h1 + (size_t)(r - 1) * H_ * B_ + SB,
                          ks * 64, ks * 64 + 64, b1, h);
                gemv1(a, w0x, g_xT + (size_t)r * D_ * B_ + SB,
                      ks * 8, ks * 8 + 8, b1, h);
            }
            cstore(a, gp + (size_t)2 * (8 * 8 * SB), ks, b1, lane); // [1][0]
#pragma unroll
            for (int i = 0; i < 8; ++i) a[i] = 0ull;
            if (r >= 1) {
                gemv1(a, w1ff, g_h1 + (size_t)(r - 1) * H_ * B_ + SB,
                      ks * 64, ks * 64 + 64, b1, h);
                if (r >= 2)
                    gemv1(a, w1, g_h2 + (size_t)(r - 2) * H_ * B_ + SB,
                          ks * 64, ks * 64 + 64, b1, h);
            }
            cstore(a, gp + (size_t)3 * (8 * 8 * SB), ks, b1, lane); // [1][1]
        }
        __syncthreads();                                       // SYNC2
        if (tid >= 256 && tid < 384) {                         // gates s1
            gates_stage(1, tid - 256, r, gp, cst, bias, j0);
            __threadfence();
            asm volatile("bar.sync 2, 128;" ::: "memory");
            if (tid == 256) atomicAdd(&g_cnt1[r], 1);
        }
        // warps 12-15 and 0-7 fall through to next round's gemv(s0) while
        // warps 8-11 finish gates(s1): MUFU overlaps FMA every half-round.
    }
    __syncthreads();

    // ---- head on CTA 0: logits = h2[:,T-1] @ Wlin^T + blin; log_softmax ----
    if (blockIdx.x == 0) {
        if (tid == 0) {
            while (ld_acq(&g_cnt0[T_]) < NCTA) {}
            while (ld_acq(&g_cnt1[T_]) < NCTA) {}
        }
        __syncthreads();
        float* hv = (float*)smem;                      // [64][521]
        float* lg = (float*)(smem + OFF_LG);           // [640]
        const float* h2l = g_h2 + (size_t)(T_ - 1) * H_ * B_;
        for (int idx = tid; idx < H_ * B_; idx += NTHR) {
            int k = idx >> 6, b = idx & 63;
            hv[b * HV_STRIDE + k] = h2l[idx];
        }
        __syncthreads();
        for (int pr = w * 40; pr < w * 40 + 40; ++pr) {
            int b = pr / OUT_, o = pr % OUT_;
            float sum = 0.f;
            for (int i = lane; i < H_; i += 32)
                sum += hv[b * HV_STRIDE + i] * Wlin[(size_t)o * H_ + i];
#pragma unroll
            for (int off = 16; off; off >>= 1)
                sum += __shfl_xor_sync(0xffffffffu, sum, off);
            if (lane == 0) lg[pr] = sum + blin[o];
        }
        __syncthreads();
        if (tid < B_) {
            float mx = -1e30f;
#pragma unroll
            for (int q = 0; q < OUT_; ++q) mx = fmaxf(mx, lg[tid * OUT_ + q]);
            float z = 0.f;
#pragma unroll
            for (int q = 0; q < OUT_; ++q) z += expf(lg[tid * OUT_ + q] - mx);
            float lse = mx + logf(z);
#pragma unroll
            for (int q = 0; q < OUT_; ++q)
                out[tid * OUT_ + q] = lg[tid * OUT_ + q] - lse;
        }
    }
}

extern "C" void kernel_launch(void* const* d_in, const int* in_sizes, int n_in,
                              void* d_out, int out_size) {
    const float* x    = (const float*)d_in[0];
    const float* Wih0 = (const float*)d_in[1];
    const float* Whh0 = (const float*)d_in[2];
    const float* bih0 = (const float*)d_in[3];
    const float* bhh0 = (const float*)d_in[4];
    const float* Wih1 = (const float*)d_in[5];
    const float* Whh1 = (const float*)d_in[6];
    const float* bih1 = (const float*)d_in[7];
    const float* bhh1 = (const float*)d_in[8];
    const float* Wlin = (const float*)d_in[9];
    const float* blin = (const float*)d_in[10];
    float* out = (float*)d_out;

    cudaFuncSetAttribute(lstm_kernel,
                         cudaFuncAttributeMaxDynamicSharedMemorySize,
                         (int)SMEM_BYTES);

    prep_kernel<<<T_, 256>>>(x);
    lstm_kernel<<<NCTA, NTHR, SMEM_BYTES>>>(Wih0, Whh0, bih0, bhh0,
                                            Wih1, Whh1, bih1, bhh1,
                                            Wlin, blin, out);
}

// round 13
// speedup vs baseline: 1.5609x; 1.5609x over previous
#include <cuda_runtime.h>
#include <cstdint>
#include <math.h>

// ---------------------------------------------------------------------------
// 2-layer LSTM (B=64, T=2048, D=64, H=512) + linear head + log_softmax.
//
// Persistent weight-stationary kernel, R11 gemv (k-parity weight sharing,
// 2 batches/lane) kept byte-for-byte. R13: SLACK-SCHEDULED SPLIT COUNTERS.
// cntA[t]=h1[t] ready, cntB[t]=h2[t] ready. Round r:
//   poll B[r-2] -> gemv L1-rec(h2[r-2]) -> poll A[r-1] -> gemv L1-ff(h1[r-1])
//   -> S1 -> [warps0-3: gates-L1 -> publish B[r-1]] || [all: gemv L0 + xff]
//   -> S2 -> [warps4-7: gates-L0 -> publish A[r]]   || [next round begins]
// B is published mid-round, consumed next round start (~40% round slack);
// A published at round end, consumed ~30% into next round. Barrier latency
// + cross-CTA jitter hide under gemv instead of being exposed (~10K cyc in
// R11). Polls are per-warp; gates overlap the other 12 warps' gemv.
// ---------------------------------------------------------------------------

namespace {
constexpr int B_   = 64;
constexpr int T_   = 2048;
constexpr int D_   = 64;
constexpr int H_   = 512;
constexpr int OUT_ = 10;
constexpr int NCTA = 128;
constexpr int NTHR = 512;                 // 16 warps = 8 k-slices x 2 b-halves
constexpr int ROWS = 16;                  // gate rows per layer per CTA
constexpr int K0   = H_ + D_;
constexpr int K1   = H_ + H_;

constexpr size_t OFF_W0  = 0;                                   // [576][16]
constexpr size_t OFF_W1  = OFF_W0 + (size_t)K0 * ROWS * 4;      //  36864
constexpr size_t OFF_GP0 = OFF_W1 + (size_t)K1 * ROWS * 4;      // 102400
constexpr size_t OFF_GP1 = OFF_GP0 + (size_t)8 * 8 * B_ * 8;    // 135168
constexpr size_t OFF_CST = OFF_GP1 + (size_t)8 * 8 * B_ * 8;    // 167936
constexpr size_t OFF_BIA = OFF_CST + 2048;                      // 169984
constexpr size_t SMEM_BYTES = OFF_BIA + 128;                    // 170112

constexpr int HV_STRIDE = 521;                  // head staging
constexpr size_t OFF_LG = (size_t)B_ * HV_STRIDE * 4;           // 133376
}

// Static device scratch (no runtime allocation).
__device__ float g_h1[(size_t)T_ * H_ * B_];   // layer0 h, [t][unit][b]
__device__ float g_h2[(size_t)T_ * H_ * B_];   // layer1 h, [t][unit][b]
__device__ float g_xT[(size_t)T_ * D_ * B_];   // x transposed, [t][k][b]
__device__ int   g_cntA[T_ + 1];               // h1[t] ready counters
__device__ int   g_cntB[T_ + 1];               // h2[t] ready counters

__device__ __forceinline__ void ffma2(uint64_t& acc, uint64_t a, uint64_t b) {
    asm("fma.rn.f32x2 %0, %1, %2, %0;" : "+l"(acc) : "l"(a), "l"(b));
}
__device__ __forceinline__ void addf2(uint64_t& acc, uint64_t a) {
    asm("add.rn.f32x2 %0, %0, %1;" : "+l"(acc) : "l"(a));
}
__device__ __forceinline__ uint64_t dup2(float x) {
    uint64_t r;
    asm("mov.b64 %0, {%1, %1};" : "=l"(r) : "f"(x));
    return r;
}
__device__ __forceinline__ float2 unpk(uint64_t v) {
    float2 f;
    asm("mov.b64 {%0, %1}, %2;" : "=f"(f.x), "=f"(f.y) : "l"(v));
    return f;
}
__device__ __forceinline__ int ld_acq(const int* p) {
    int v;
    asm volatile("ld.global.acquire.gpu.b32 %0, [%1];" : "=r"(v) : "l"(p));
    return v;
}
// Per-warp wait: lane 0 polls, warp converges after.
__device__ __forceinline__ void wait_warp(const int* p) {
    if ((threadIdx.x & 31) == 0) {
        while (ld_acq(p) < NCTA) {}
    }
    __syncwarp();
}
__device__ __forceinline__ float fast_sigmoid(float x) {
    return __fdividef(1.f, 1.f + __expf(-x));
}
__device__ __forceinline__ float fast_tanh(float x) {
    float a = fabsf(x);
    float t = __expf(-2.f * a);
    float r = __fdividef(1.f - t, 1.f + t);
    return copysignf(r, x);
}

// k-parity GEMV (R11): lane-half h handles rows k+h for its 2 batches.
// Per k-pair: 1 coalesced LDG.64 + 4 LDS.128 shared across both halves.
__device__ __forceinline__ void gemv2k(uint64_t aA[8], uint64_t aB[8],
                                       const float* __restrict__ wsm,
                                       const float* __restrict__ in,
                                       int kb, int ke, int b2, int h) {
#pragma unroll 8
    for (int k = kb; k < ke; k += 2) {
        int kk = k + h;
        float2 v = *(const float2*)(in + (size_t)kk * B_ + b2);
        uint64_t x0 = dup2(v.x);
        uint64_t x1 = dup2(v.y);
        const ulonglong2* wv = (const ulonglong2*)(wsm + (size_t)kk * ROWS);
#pragma unroll
        for (int q = 0; q < 4; ++q) {
            ulonglong2 wp = wv[q];
            ffma2(aA[2 * q],     wp.x, x0);
            ffma2(aA[2 * q + 1], wp.y, x0);
            ffma2(aB[2 * q],     wp.x, x1);
            ffma2(aB[2 * q + 1], wp.y, x1);
        }
    }
}

// Combine k-parities (shfl 16) and store; lanes 0-15 write contiguous.
__device__ __forceinline__ void cstore(uint64_t aA[8], uint64_t aB[8],
                                       uint64_t* __restrict__ gp,
                                       int ks, int b2, int lane) {
#pragma unroll
    for (int p = 0; p < 8; ++p) {
        unsigned long long oA = __shfl_xor_sync(0xffffffffu,
                                                (unsigned long long)aA[p], 16);
        unsigned long long oB = __shfl_xor_sync(0xffffffffu,
                                                (unsigned long long)aB[p], 16);
        addf2(aA[p], (uint64_t)oA);
        addf2(aB[p], (uint64_t)oB);
    }
    if (lane < 16) {
#pragma unroll
        for (int p = 0; p < 8; ++p) {
            *(ulonglong2*)(gp + (size_t)(ks * 8 + p) * B_ + b2)
                = make_ulonglong2(aA[p], aB[p]);
        }
    }
}

// Gates for ONE layer: 128 threads, it = (pair-half p, batch b).
__device__ __forceinline__ void gates_layer(const uint64_t* __restrict__ gpl,
                                            float* __restrict__ cst,
                                            const float* __restrict__ bb,
                                            int it, int t, int j0,
                                            float* __restrict__ hout,
                                            int cbase) {
    int p = it >> 6, b = it & 63;
    uint64_t sg[4];
#pragma unroll
    for (int g = 0; g < 4; ++g) {
        int pi = g * 2 + p;
        uint64_t v = gpl[(size_t)pi * B_ + b];
#pragma unroll
        for (int ss = 1; ss < 8; ++ss)
            addf2(v, gpl[((size_t)ss * 8 + pi) * B_ + b]);
        sg[g] = v;
    }
    float2 vi = unpk(sg[0]), vf = unpk(sg[1]);
    float2 vg = unpk(sg[2]), vo = unpk(sg[3]);
#pragma unroll
    for (int j2 = 0; j2 < 2; ++j2) {
        int j = 2 * p + j2;
        float gi = (j2 ? vi.y : vi.x) + bb[j];
        float gf = (j2 ? vf.y : vf.x) + bb[4 + j];
        float gg = (j2 ? vg.y : vg.x) + bb[8 + j];
        float go = (j2 ? vo.y : vo.x) + bb[12 + j];
        float si = fast_sigmoid(gi);
        float sf = fast_sigmoid(gf);
        float so = fast_sigmoid(go);
        float tg = fast_tanh(gg);
        int ci = cbase + j * 64 + b;
        float c = sf * cst[ci] + si * tg;
        cst[ci] = c;
        hout[(size_t)t * H_ * B_ + (size_t)(j0 + j) * B_ + b]
            = so * fast_tanh(c);
    }
}

// prep: zero counters + transpose x[b][t][k] -> g_xT[t][k][b]
__global__ void prep_kernel(const float* __restrict__ x) {
    __shared__ float tile[64][65];
    int t = blockIdx.x;
    if (threadIdx.x == 0) {
        g_cntA[t] = 0;
        g_cntB[t] = 0;
        if (t == 0) { g_cntA[T_] = 0; g_cntB[T_] = 0; }
    }
    for (int i = threadIdx.x; i < 64 * 64; i += blockDim.x) {
        int b = i >> 6, k = i & 63;
        tile[b][k] = x[(size_t)b * T_ * D_ + (size_t)t * D_ + k];
    }
    __syncthreads();
    for (int i = threadIdx.x; i < 64 * 64; i += blockDim.x) {
        int k = i >> 6, b = i & 63;
        g_xT[(size_t)t * D_ * B_ + (size_t)k * B_ + b] = tile[b][k];
    }
}

__global__ __launch_bounds__(NTHR, 1)
void lstm_kernel(const float* __restrict__ Wih0, const float* __restrict__ Whh0,
                 const float* __restrict__ bih0, const float* __restrict__ bhh0,
                 const float* __restrict__ Wih1, const float* __restrict__ Whh1,
                 const float* __restrict__ bih1, const float* __restrict__ bhh1,
                 const float* __restrict__ Wlin, const float* __restrict__ blin,
                 float* __restrict__ out) {
    extern __shared__ unsigned char smem[];
    float*    w0   = (float*)(smem + OFF_W0);      // [K0][16]
    float*    w1   = (float*)(smem + OFF_W1);      // [K1][16]
    uint64_t* gp0  = (uint64_t*)(smem + OFF_GP0);  // [8 slice][8 pair][64 b]
    uint64_t* gp1  = (uint64_t*)(smem + OFF_GP1);  // [8 slice][8 pair][64 b]
    float*    cst  = (float*)(smem + OFF_CST);     // [2][4][64]
    float*    bias = (float*)(smem + OFF_BIA);     // [2][16]

    const int tid  = threadIdx.x;
    const int lane = tid & 31;
    const int w    = tid >> 5;                     // warp 0..15
    const int ks   = w & 7;                        // k-slice 0..7
    const int bh   = w >> 3;                       // batch half 0..1
    const int h    = lane >> 4;                    // k-parity 0..1
    const int m    = lane & 15;
    const int b2   = bh * 32 + 2 * m;              // batches b2, b2+1
    const int j0   = blockIdx.x * 4;

    // ---- load weights (row r = gate*4 + j; k<H_ -> W_hh else W_ih) ----
    for (int idx = tid; idx < K0 * ROWS; idx += NTHR) {
        int k = idx >> 4, rr = idx & 15;
        int row = (rr >> 2) * H_ + j0 + (rr & 3);
        w0[idx] = (k < H_) ? Whh0[(size_t)row * H_ + k]
                           : Wih0[(size_t)row * D_ + (k - H_)];
    }
    for (int idx = tid; idx < K1 * ROWS; idx += NTHR) {
        int k = idx >> 4, rr = idx & 15;
        int row = (rr >> 2) * H_ + j0 + (rr & 3);
        w1[idx] = (k < H_) ? Whh1[(size_t)row * H_ + k]
                           : Wih1[(size_t)row * H_ + (k - H_)];
    }
    if (tid < 32) {
        int l = tid >> 4, rr = tid & 15;
        int row = (rr >> 2) * H_ + j0 + (rr & 3);
        bias[tid] = l ? (bih1[row] + bhh1[row]) : (bih0[row] + bhh0[row]);
    }
    cst[tid] = 0.f;                                // exactly 512 entries
    __syncthreads();

    const float* w0x  = w0 + (size_t)H_ * ROWS;    // layer0 x-ff rows
    const float* w1ff = w1 + (size_t)H_ * ROWS;    // layer1 h1-ff rows

#pragma unroll 1
    for (int r = 0; r <= T_; ++r) {
        uint64_t aA[8], aB[8];

        // ===== layer 1 gemv (step r-1): rec over h2[r-2], ff over h1[r-1] ==
#pragma unroll
        for (int i = 0; i < 8; ++i) { aA[i] = 0ull; aB[i] = 0ull; }
        if (r >= 2) {
            wait_warp(&g_cntB[r - 2]);             // ~40% round slack
            gemv2k(aA, aB, w1, g_h2 + (size_t)(r - 2) * H_ * B_,
                   ks * 64, ks * 64 + 64, b2, h);
        }
        if (r >= 1) {
            wait_warp(&g_cntA[r - 1]);             // buried ~30% into round
            gemv2k(aA, aB, w1ff, g_h1 + (size_t)(r - 1) * H_ * B_,
                   ks * 64, ks * 64 + 64, b2, h);
        }
        cstore(aA, aB, gp1, ks, b2, lane);
        __syncthreads();                           // S1

        // ===== gates-L1 (warps 0-3) overlapped with layer-0 gemv ==========
        if (w < 4) {
            if (r >= 1)
                gates_layer(gp1, cst, bias + 16, tid, r - 1, j0, g_h2, 256);
            __threadfence();
            asm volatile("bar.sync 3, 128;" ::: "memory");
            if (tid == 0 && r >= 1) atomicAdd(&g_cntB[r - 1], 1);
        }

        // ===== layer 0 gemv (step r): rec over h1[r-1] + x-ff =============
#pragma unroll
        for (int i = 0; i < 8; ++i) { aA[i] = 0ull; aB[i] = 0ull; }
        if (r < T_) {
            if (r >= 1)
                gemv2k(aA, aB, w0, g_h1 + (size_t)(r - 1) * H_ * B_,
                       ks * 64, ks * 64 + 64, b2, h);
            gemv2k(aA, aB, w0x, g_xT + (size_t)r * D_ * B_,
                   ks * 8, ks * 8 + 8, b2, h);
        }
        cstore(aA, aB, gp0, ks, b2, lane);
        __syncthreads();                           // S2

        // ===== gates-L0 (warps 4-7) overlapped with next round's L1 gemv ==
        if (w >= 4 && w < 8) {
            if (r < T_)
                gates_layer(gp0, cst, bias, tid - 128, r, j0, g_h1, 0);
            __threadfence();
            asm volatile("bar.sync 4, 128;" ::: "memory");
            if (tid == 128 && r < T_) atomicAdd(&g_cntA[r], 1);
        }
        // warps 0-3 and 8-15 flow straight into round r+1's L1 gemv.
    }
    __syncthreads();

    // ---- head on CTA 0: logits = h2[:,T-1] @ Wlin^T + blin; log_softmax ----
    if (blockIdx.x == 0) {
        if (tid == 0) {
            while (ld_acq(&g_cntB[T_ - 1]) < NCTA) {}
        }
        __syncthreads();
        float* hv = (float*)smem;                      // [64][521]
        float* lg = (float*)(smem + OFF_LG);           // [640]
        const float* h2l = g_h2 + (size_t)(T_ - 1) * H_ * B_;
        for (int idx = tid; idx < H_ * B_; idx += NTHR) {
            int k = idx >> 6, b = idx & 63;
            hv[b * HV_STRIDE + k] = h2l[idx];
        }
        __syncthreads();
        for (int pr = w * 40; pr < w * 40 + 40; ++pr) {
            int b = pr / OUT_, o = pr % OUT_;
            float sum = 0.f;
            for (int i = lane; i < H_; i += 32)
                sum += hv[b * HV_STRIDE + i] * Wlin[(size_t)o * H_ + i];
#pragma unroll
            for (int off = 16; off; off >>= 1)
                sum += __shfl_xor_sync(0xffffffffu, sum, off);
            if (lane == 0) lg[pr] = sum + blin[o];
        }
        __syncthreads();
        if (tid < B_) {
            float mx = -1e30f;
#pragma unroll
            for (int q = 0; q < OUT_; ++q) mx = fmaxf(mx, lg[tid * OUT_ + q]);
            float z = 0.f;
#pragma unroll
            for (int q = 0; q < OUT_; ++q) z += expf(lg[tid * OUT_ + q] - mx);
            float lse = mx + logf(z);
#pragma unroll
            for (int q = 0; q < OUT_; ++q)
                out[tid * OUT_ + q] = lg[tid * OUT_ + q] - lse;
        }
    }
}

extern "C" void kernel_launch(void* const* d_in, const int* in_sizes, int n_in,
                              void* d_out, int out_size) {
    const float* x    = (const float*)d_in[0];
    const float* Wih0 = (const float*)d_in[1];
    const float* Whh0 = (const float*)d_in[2];
    const float* bih0 = (const float*)d_in[3];
    const float* bhh0 = (const float*)d_in[4];
    const float* Wih1 = (const float*)d_in[5];
    const float* Whh1 = (const float*)d_in[6];
    const float* bih1 = (const float*)d_in[7];
    const float* bhh1 = (const float*)d_in[8];
    const float* Wlin = (const float*)d_in[9];
    const float* blin = (const float*)d_in[10];
    float* out = (float*)d_out;

    cudaFuncSetAttribute(lstm_kernel,
                         cudaFuncAttributeMaxDynamicSharedMemorySize,
                         (int)SMEM_BYTES);

    prep_kernel<<<T_, 256>>>(x);
    lstm_kernel<<<NCTA, NTHR, SMEM_BYTES>>>(Wih0, Whh0, bih0, bhh0,
                                            Wih1, Whh1, bih1, bhh1,
                                            Wlin, blin, out);
}